// round 16
// baseline (speedup 1.0000x reference)
#include <cuda_runtime.h>
#include <cuda_bf16.h>
#include <math.h>
#include <cstdint>

#define SEQ   512
#define BATCH 64
#define EMB   512
#define HID   1024
#define G3    3072
#define NOUT  5
#define MTOT  (SEQ*BATCH)
#define NBLK  288            // 48 N-tiles x 6 K-slices; 2 blocks/SM co-resident
#define NKS   6
#define NGRP  24             // barrier tree: 24 groups x 12 blocks
#define APITCH 72            // bf16 per smem row (pad: conflict-free frag loads)
#define TILE_E (64 * APITCH) // elements per 64x64 (padded) tile

// Scratch (static __device__ arrays: allowed; no runtime allocation)
__device__ float g_xg[(size_t)MTOT * G3];            // [S*B, 3H] input gates (+b_ih)
__device__ float g_h[2][BATCH * HID];                // ping-pong hidden state (fp32)
__device__ __nv_bfloat16 g_hhi[BATCH * HID];         // bf16 split of current h
__device__ __nv_bfloat16 g_hlo[BATCH * HID];
__device__ __nv_bfloat16 g_whi[(size_t)G3 * HID];    // bf16 split of W_hh
__device__ __nv_bfloat16 g_wlo[(size_t)G3 * HID];
__device__ __nv_bfloat16 g_wihhi[(size_t)G3 * EMB];  // bf16 split of W_ih
__device__ __nv_bfloat16 g_wihlo[(size_t)G3 * EMB];
__device__ __nv_bfloat16 g_xehi[(size_t)MTOT * EMB]; // bf16 split of gathered embeddings
__device__ __nv_bfloat16 g_xelo[(size_t)MTOT * EMB];
__device__ float g_part[NKS][BATCH * G3];            // K-split partials of h @ W_hh^T

// tree barrier state (monotonic counters: no reset, replay-safe)
__device__ unsigned g_grp_cnt[NGRP];
__device__ unsigned g_master_cnt = 0;
__device__ unsigned g_bar_sense = 0;

__device__ __forceinline__ float sigf(float x) { return 1.f / (1.f + expf(-x)); }

__device__ __forceinline__ unsigned ld_acquire_u32(const unsigned* p)
{
    unsigned v;
    asm volatile("ld.acquire.gpu.u32 %0, [%1];" : "=r"(v) : "l"(p) : "memory");
    return v;
}
__device__ __forceinline__ void st_release_u32(unsigned* p, unsigned v)
{
    asm volatile("st.release.gpu.u32 [%0], %1;" :: "l"(p), "r"(v) : "memory");
}

// Tree grid barrier: NGRP parallel group counters -> 1 master counter -> sense.
__device__ __forceinline__ void grid_sync(unsigned* s_sense, int grp)
{
    __syncthreads();
    if (threadIdx.x == 0) {
        const unsigned target = *s_sense + 1u;
        __threadfence();                                  // publish block's writes
        const unsigned r = atomicAdd(&g_grp_cnt[grp], 1u);
        if ((r % (NBLK / NGRP)) == (NBLK / NGRP) - 1u) {  // last of group
            const unsigned m = atomicAdd(&g_master_cnt, 1u);
            if ((m % NGRP) == NGRP - 1u) {                // last group
                __threadfence();
                st_release_u32(&g_bar_sense, target);
            }
        }
        while (ld_acquire_u32(&g_bar_sense) != target) { }
        *s_sense = target;
        __threadfence();                                  // acquire side
    }
    __syncthreads();
}

__device__ __forceinline__ void mma_bf16(float c[4], uint32_t a0, uint32_t a1,
                                         uint32_t a2, uint32_t a3,
                                         uint32_t b0, uint32_t b1)
{
    asm volatile(
        "mma.sync.aligned.m16n8k16.row.col.f32.bf16.bf16.f32 "
        "{%0,%1,%2,%3}, {%4,%5,%6,%7}, {%8,%9}, {%0,%1,%2,%3};"
        : "+f"(c[0]), "+f"(c[1]), "+f"(c[2]), "+f"(c[3])
        : "r"(a0), "r"(a1), "r"(a2), "r"(a3), "r"(b0), "r"(b1));
}

__device__ __forceinline__ void cp_async16(uint32_t saddr, const void* g)
{
    asm volatile("cp.async.cg.shared.global [%0], [%1], 16;" :: "r"(saddr), "l"(g));
}
__device__ __forceinline__ void cp_commit() { asm volatile("cp.async.commit_group;"); }
__device__ __forceinline__ void cp_wait0()  { asm volatile("cp.async.wait_group 0;"); }
__device__ __forceinline__ void cp_wait1()  { asm volatile("cp.async.wait_group 1;"); }

// stage one 64x64 bf16 tile (sync path): thread copies rows r0, r1, 16B chunk q
__device__ __forceinline__ void stage_tile(
    __nv_bfloat16 (*s)[APITCH], const __nv_bfloat16* g, int ld,
    int r0, int r1, int q)
{
    uint4 v = *(const uint4*)(g + (size_t)r0 * ld + q * 8);
    *(uint2*)&s[r0][q * 8]     = make_uint2(v.x, v.y);
    *(uint2*)&s[r0][q * 8 + 4] = make_uint2(v.z, v.w);
    v = *(const uint4*)(g + (size_t)r1 * ld + q * 8);
    *(uint2*)&s[r1][q * 8]     = make_uint2(v.x, v.y);
    *(uint2*)&s[r1][q * 8 + 4] = make_uint2(v.z, v.w);
}

// 64x64x64 bf16x3 compute; A/W are padded-tile base pointers (APITCH stride)
__device__ __forceinline__ void mma_tile(
    float c[4][4],
    const __nv_bfloat16* Ahi, const __nv_bfloat16* Alo,
    const __nv_bfloat16* Whi, const __nv_bfloat16* Wlo,
    int wm, int wn, int gq, int tg)
{
#pragma unroll
    for (int kk = 0; kk < 4; kk++) {
        const int kb = kk * 16 + tg * 2;
        const int ar0 = (wm * 16 + gq) * APITCH;
        const int ar8 = ar0 + 8 * APITCH;
        const uint32_t ahi0 = *(const uint32_t*)&Ahi[ar0 + kb];
        const uint32_t ahi1 = *(const uint32_t*)&Ahi[ar8 + kb];
        const uint32_t ahi2 = *(const uint32_t*)&Ahi[ar0 + kb + 8];
        const uint32_t ahi3 = *(const uint32_t*)&Ahi[ar8 + kb + 8];
        const uint32_t alo0 = *(const uint32_t*)&Alo[ar0 + kb];
        const uint32_t alo1 = *(const uint32_t*)&Alo[ar8 + kb];
        const uint32_t alo2 = *(const uint32_t*)&Alo[ar0 + kb + 8];
        const uint32_t alo3 = *(const uint32_t*)&Alo[ar8 + kb + 8];
#pragma unroll
        for (int nf = 0; nf < 4; nf++) {
            const int nr = (wn * 32 + nf * 8 + gq) * APITCH;
            const uint32_t bhi0 = *(const uint32_t*)&Whi[nr + kb];
            const uint32_t bhi1 = *(const uint32_t*)&Whi[nr + kb + 8];
            const uint32_t blo0 = *(const uint32_t*)&Wlo[nr + kb];
            const uint32_t blo1 = *(const uint32_t*)&Wlo[nr + kb + 8];
            mma_bf16(c[nf], ahi0, ahi1, ahi2, ahi3, bhi0, bhi1);
            mma_bf16(c[nf], ahi0, ahi1, ahi2, ahi3, blo0, blo1);
            mma_bf16(c[nf], alo0, alo1, alo2, alo3, bhi0, bhi1);
        }
    }
}

// ---------------------------------------------------------------------------
// One-time weight splits
// ---------------------------------------------------------------------------
__global__ void split_whh_kernel(const float* __restrict__ W)
{
    const size_t i = (size_t)blockIdx.x * blockDim.x + threadIdx.x;
    if (i < (size_t)G3 * HID) {
        const float w = W[i];
        const __nv_bfloat16 hi = __float2bfloat16(w);
        g_whi[i] = hi;
        g_wlo[i] = __float2bfloat16(w - __bfloat162float(hi));
    }
}

__global__ void split_wih_kernel(const float* __restrict__ W)
{
    const size_t i = (size_t)blockIdx.x * blockDim.x + threadIdx.x;
    if (i < (size_t)G3 * EMB) {
        const float w = W[i];
        const __nv_bfloat16 hi = __float2bfloat16(w);
        g_wihhi[i] = hi;
        g_wihlo[i] = __float2bfloat16(w - __bfloat162float(hi));
    }
}

// ---------------------------------------------------------------------------
// Gather embeddings per token and split to bf16 hi/lo. 1 thread = 4 elements.
// ---------------------------------------------------------------------------
__global__ void gather_split_kernel(const int* __restrict__ text,
                                    const float* __restrict__ emb)
{
    const int i = blockIdx.x * 256 + threadIdx.x;
    const int row = i >> 7;
    const int c4 = (i & 127) * 4;
    const int tok = text[row];
    const float4 v = *(const float4*)(emb + (size_t)tok * EMB + c4);

    const __nv_bfloat16 h0 = __float2bfloat16(v.x);
    const __nv_bfloat16 h1 = __float2bfloat16(v.y);
    const __nv_bfloat16 h2 = __float2bfloat16(v.z);
    const __nv_bfloat16 h3 = __float2bfloat16(v.w);
    const __nv_bfloat16 l0 = __float2bfloat16(v.x - __bfloat162float(h0));
    const __nv_bfloat16 l1 = __float2bfloat16(v.y - __bfloat162float(h1));
    const __nv_bfloat16 l2 = __float2bfloat16(v.z - __bfloat162float(h2));
    const __nv_bfloat16 l3 = __float2bfloat16(v.w - __bfloat162float(h3));

    const size_t off = (size_t)row * EMB + c4;
    __nv_bfloat162 p;
    p.x = h0; p.y = h1; *(__nv_bfloat162*)&g_xehi[off]     = p;
    p.x = h2; p.y = h3; *(__nv_bfloat162*)&g_xehi[off + 2] = p;
    p.x = l0; p.y = l1; *(__nv_bfloat162*)&g_xelo[off]     = p;
    p.x = l2; p.y = l3; *(__nv_bfloat162*)&g_xelo[off + 2] = p;
}

// ---------------------------------------------------------------------------
// xg = xemb @ W_ih^T + b_ih  (M=32768, N=3072, K=512) in bf16x3 tensor cores
// ---------------------------------------------------------------------------
__global__ void __launch_bounds__(256, 2) xg_mma_kernel(const float* __restrict__ bias)
{
    __shared__ __align__(16) __nv_bfloat16 sAhi[64][APITCH];
    __shared__ __align__(16) __nv_bfloat16 sAlo[64][APITCH];
    __shared__ __align__(16) __nv_bfloat16 sBhi[64][APITCH];
    __shared__ __align__(16) __nv_bfloat16 sBlo[64][APITCH];

    const int tid = threadIdx.x;
    const int n0 = blockIdx.x * 64;
    const int m0 = blockIdx.y * 64;

    const int warp = tid >> 5;
    const int lane = tid & 31;
    const int wm = warp >> 1;
    const int wn = warp & 1;
    const int gq = lane >> 2;
    const int tg = lane & 3;

    const int st_row0 = tid >> 3;
    const int st_q0   = tid & 7;
    const int st_row1 = st_row0 + 32;

    float c[4][4];
#pragma unroll
    for (int nf = 0; nf < 4; nf++)
#pragma unroll
        for (int i = 0; i < 4; i++) c[nf][i] = 0.f;

    for (int ch = 0; ch < 8; ch++) {
        const int k0 = ch * 64;
        __syncthreads();
        stage_tile(sAhi, g_xehi + (size_t)m0 * EMB + k0, EMB, st_row0, st_row1, st_q0);
        stage_tile(sAlo, g_xelo + (size_t)m0 * EMB + k0, EMB, st_row0, st_row1, st_q0);
        stage_tile(sBhi, g_wihhi + (size_t)n0 * EMB + k0, EMB, st_row0, st_row1, st_q0);
        stage_tile(sBlo, g_wihlo + (size_t)n0 * EMB + k0, EMB, st_row0, st_row1, st_q0);
        __syncthreads();
        mma_tile(c, &sAhi[0][0], &sAlo[0][0], &sBhi[0][0], &sBlo[0][0], wm, wn, gq, tg);
    }

    const int m0r = m0 + wm * 16 + gq;
#pragma unroll
    for (int nf = 0; nf < 4; nf++) {
        const int n = n0 + wn * 32 + nf * 8 + tg * 2;
        const float b0 = bias[n], b1 = bias[n + 1];
        *(float2*)&g_xg[(size_t)m0r * G3 + n]       = make_float2(c[nf][0] + b0, c[nf][1] + b1);
        *(float2*)&g_xg[(size_t)(m0r + 8) * G3 + n] = make_float2(c[nf][2] + b0, c[nf][3] + b1);
    }
}

// ---------------------------------------------------------------------------
// Persistent kernel: 288 blocks (2/SM), W_hh slice (<=3 chunks) resident in
// smem; cp.async A double-buffer; tree barrier; xg prefetch over barrier.
// Block b: N-tile (b%48)*64, K-slice b/48 of {192,192,192,192,128,128}.
// Smem/block: sW 6 tiles + sA 4 tiles = 92,160 B -> 2 blocks/SM.
// ---------------------------------------------------------------------------
#define SMEM_BYTES ((6 + 4) * TILE_E * 2)

__global__ void __launch_bounds__(256, 2) gru_persistent(
    const float* __restrict__ b_hh,
    const float* __restrict__ Wfc, const float* __restrict__ bfc,
    float* __restrict__ out)
{
    extern __shared__ __align__(16) __nv_bfloat16 smem[];
    __nv_bfloat16* sW = smem;                // 6 tiles (chunk*2 + hi/lo)
    __nv_bfloat16* sA = smem + 6 * TILE_E;   // 4 tiles (buf*2 + hi/lo)
    __shared__ unsigned s_sense;

    const int tid = threadIdx.x;
    const int bid = blockIdx.x;
    const int grp = bid % NGRP;

    if (tid == 0) s_sense = ld_acquire_u32(&g_bar_sense);
    __syncthreads();

    const int n0 = (bid % 48) * 64;
    const int ks = bid / 48;
    const int k_start = (ks < 4) ? ks * 192 : 768 + (ks - 4) * 128;
    const int nchunks = (ks < 4) ? 3 : 2;

    const int warp = tid >> 5;
    const int lane = tid & 31;
    const int wm = warp >> 1;
    const int wn = warp & 1;
    const int gq = lane >> 2;
    const int tg = lane & 3;

    const int st_row0 = tid >> 3;          // 0..31
    const int st_q0   = tid & 7;           // 0..7
    const int st_row1 = st_row0 + 32;      // 32..63

    // ---- one-time: load W slice (hi/lo) into resident smem ----
    for (int ch = 0; ch < nchunks; ch++) {
        const int k0 = k_start + ch * 64;
        stage_tile((__nv_bfloat16(*)[APITCH])(sW + (ch * 2 + 0) * TILE_E),
                   g_whi + (size_t)n0 * HID + k0, HID, st_row0, st_row1, st_q0);
        stage_tile((__nv_bfloat16(*)[APITCH])(sW + (ch * 2 + 1) * TILE_E),
                   g_wlo + (size_t)n0 * HID + k0, HID, st_row0, st_row1, st_q0);
    }

    // h0 = 0 (fp32 and bf16 splits)
    for (int i = bid * 256 + tid; i < BATCH * HID; i += NBLK * 256) {
        g_h[0][i] = 0.f;
        g_hhi[i] = __float2bfloat16(0.f);
        g_hlo[i] = __float2bfloat16(0.f);
    }
    grid_sync(&s_sense, grp);   // also orders W-staging before first MMA

    const uint32_t sA_b = (uint32_t)__cvta_generic_to_shared(sA);
    const uint32_t aoff0 = (uint32_t)(st_row0 * APITCH + st_q0 * 8) * 2;
    const uint32_t aoff1 = (uint32_t)(st_row1 * APITCH + st_q0 * 8) * 2;
    const uint32_t tb = (uint32_t)TILE_E * 2;   // tile bytes

    for (int t = 0; t < SEQ; t++) {
        const int par = t & 1;

        // prologue: async-stage A chunk 0 into buf 0
        {
            const int k0 = k_start;
            const __nv_bfloat16* hhi = g_hhi + k0 + st_q0 * 8;
            const __nv_bfloat16* hlo = g_hlo + k0 + st_q0 * 8;
            cp_async16(sA_b + aoff0,          hhi + (size_t)st_row0 * HID);
            cp_async16(sA_b + aoff1,          hhi + (size_t)st_row1 * HID);
            cp_async16(sA_b + tb + aoff0,     hlo + (size_t)st_row0 * HID);
            cp_async16(sA_b + tb + aoff1,     hlo + (size_t)st_row1 * HID);
            cp_commit();
        }

        float c[4][4];
#pragma unroll
        for (int nf = 0; nf < 4; nf++)
#pragma unroll
            for (int i = 0; i < 4; i++) c[nf][i] = 0.f;

        for (int ch = 0; ch < nchunks; ch++) {
            if (ch + 1 < nchunks) {
                const int k0 = k_start + (ch + 1) * 64;
                const uint32_t dst = sA_b + ((ch + 1) & 1) * 2 * tb;
                const __nv_bfloat16* hhi = g_hhi + k0 + st_q0 * 8;
                const __nv_bfloat16* hlo = g_hlo + k0 + st_q0 * 8;
                cp_async16(dst + aoff0,      hhi + (size_t)st_row0 * HID);
                cp_async16(dst + aoff1,      hhi + (size_t)st_row1 * HID);
                cp_async16(dst + tb + aoff0, hlo + (size_t)st_row0 * HID);
                cp_async16(dst + tb + aoff1, hlo + (size_t)st_row1 * HID);
                cp_commit();
                cp_wait1();
            } else {
                cp_wait0();
            }
            __syncthreads();
            const __nv_bfloat16* Ahi = sA + ((ch & 1) * 2 + 0) * TILE_E;
            const __nv_bfloat16* Alo = sA + ((ch & 1) * 2 + 1) * TILE_E;
            const __nv_bfloat16* Whi = sW + (ch * 2 + 0) * TILE_E;
            const __nv_bfloat16* Wlo = sW + (ch * 2 + 1) * TILE_E;
            mma_tile(c, Ahi, Alo, Whi, Wlo, wm, wn, gq, tg);
            __syncthreads();
        }

        // writeback partials
        {
            float* outp = g_part[ks];
            const int m0r = wm * 16 + gq;
#pragma unroll
            for (int nf = 0; nf < 4; nf++) {
                const int n = n0 + wn * 32 + nf * 8 + tg * 2;
                *(float2*)&outp[(size_t)m0r * G3 + n]       = make_float2(c[nf][0], c[nf][1]);
                *(float2*)&outp[(size_t)(m0r + 8) * G3 + n] = make_float2(c[nf][2], c[nf][3]);
            }
        }

        // ---- prefetch xg for the gates phase (overlaps DRAM latency with
        //      the barrier wait) ----
        float pxr[2], pxz[2], pxn[2];
        int pidx[2];
        int np = 0;
        for (int idx = bid * 256 + tid; idx < BATCH * HID; idx += NBLK * 256) {
            const int b = idx >> 10;
            const int j = idx & 1023;
            const float* xg = g_xg + ((size_t)t * BATCH + b) * G3;
            pxr[np] = xg[j];
            pxz[np] = xg[HID + j];
            pxn[np] = xg[2 * HID + j];
            pidx[np] = idx;
            np++;
        }

        grid_sync(&s_sense, grp);

        // ---- Gates phase ----
        for (int e = 0; e < np; e++) {
            const int idx = pidx[e];
            const int b = idx >> 10;
            const int j = idx & 1023;

            float hr = b_hh[j];
            float hz = b_hh[HID + j];
            float hn = b_hh[2 * HID + j];
#pragma unroll
            for (int p = 0; p < NKS; p++) {
                const float* pp = g_part[p] + (size_t)b * G3;
                hr += pp[j];
                hz += pp[HID + j];
                hn += pp[2 * HID + j];
            }

            const float r = sigf(pxr[e] + hr);
            const float z = sigf(pxz[e] + hz);
            const float n = tanhf(pxn[e] + r * hn);

            const float hprev = g_h[par][idx];
            const float hnew = (1.f - z) * n + z * hprev;
            g_h[par ^ 1][idx] = hnew;
            const __nv_bfloat16 hi = __float2bfloat16(hnew);
            g_hhi[idx] = hi;
            g_hlo[idx] = __float2bfloat16(hnew - __bfloat162float(hi));
        }

        grid_sync(&s_sense, grp);
    }

    // ---- Final FC (h_last in g_h[0] after t=511) ----
    if (bid < BATCH) {
        const int w = tid >> 5;
        const int ln = tid & 31;
        if (w < NOUT) {
            const float* h = g_h[0] + (size_t)bid * HID;
            const float* wr = Wfc + (size_t)w * HID;
            float s = 0.f;
            for (int k = ln; k < HID; k += 32) s += h[k] * wr[k];
#pragma unroll
            for (int o = 16; o > 0; o >>= 1) s += __shfl_xor_sync(0xffffffff, s, o);
            if (ln == 0) out[bid * NOUT + w] = s + bfc[w];
        }
    }
}

// ---------------------------------------------------------------------------
extern "C" void kernel_launch(void* const* d_in, const int* in_sizes, int n_in,
                              void* d_out, int out_size)
{
    const int*   text  = (const int*)d_in[0];
    const float* emb   = (const float*)d_in[1];
    const float* W_ih  = (const float*)d_in[2];
    const float* W_hh  = (const float*)d_in[3];
    const float* b_ih  = (const float*)d_in[4];
    const float* b_hh  = (const float*)d_in[5];
    const float* W_fc  = (const float*)d_in[6];
    const float* b_fc  = (const float*)d_in[7];
    float* out = (float*)d_out;

    // allow 92KB dynamic smem for the persistent kernel (idempotent)
    cudaFuncSetAttribute(gru_persistent,
                         cudaFuncAttributeMaxDynamicSharedMemorySize, SMEM_BYTES);

    // 0) one-time splits (bf16 hi/lo)
    split_whh_kernel<<<(G3 * HID + 255) / 256, 256>>>(W_hh);
    split_wih_kernel<<<(G3 * EMB + 255) / 256, 256>>>(W_ih);
    gather_split_kernel<<<(MTOT * EMB / 4 + 255) / 256, 256>>>(text, emb);

    // 1) input-side gate activations: bf16x3 tensor-core GEMM
    xg_mma_kernel<<<dim3(48, 512), 256>>>(b_ih);

    // 2) persistent: occ-2 + W-resident smem + tree barrier + xg prefetch
    gru_persistent<<<NBLK, 256, SMEM_BYTES>>>(b_hh, W_fc, b_fc, out);
}

// round 17
// speedup vs baseline: 1.0259x; 1.0259x over previous
#include <cuda_runtime.h>
#include <cuda_bf16.h>
#include <math.h>
#include <cstdint>

#define SEQ   512
#define BATCH 64
#define EMB   512
#define HID   1024
#define G3    3072
#define NOUT  5
#define MTOT  (SEQ*BATCH)
#define NBLK  144            // 48 N-tiles x 3 K-slices; all co-resident, occ 1
#define NKS   3
#define NGRP  12             // full-barrier tree: 12 groups x 12 blocks
#define SGRP  6              // slice-barrier tree: 6 groups x 8 blocks (48/slice)
#define APITCH 72            // bf16 per smem row (pad: conflict-free frag loads)
#define TILE_E (64 * APITCH) // elements per 64x64 (padded) tile

// Scratch (static __device__ arrays: allowed; no runtime allocation)
__device__ float g_xg[(size_t)MTOT * G3];            // [S*B, 3H] input gates (+b_ih)
__device__ float g_h[2][BATCH * HID];                // ping-pong hidden state (fp32)
__device__ __nv_bfloat16 g_hhi[BATCH * HID];         // bf16 split of current h
__device__ __nv_bfloat16 g_hlo[BATCH * HID];
__device__ __nv_bfloat16 g_whi[(size_t)G3 * HID];    // bf16 split of W_hh
__device__ __nv_bfloat16 g_wlo[(size_t)G3 * HID];
__device__ __nv_bfloat16 g_wihhi[(size_t)G3 * EMB];  // bf16 split of W_ih
__device__ __nv_bfloat16 g_wihlo[(size_t)G3 * EMB];
__device__ __nv_bfloat16 g_xehi[(size_t)MTOT * EMB]; // bf16 split of gathered embeddings
__device__ __nv_bfloat16 g_xelo[(size_t)MTOT * EMB];
__device__ float g_part[NKS][BATCH * G3];            // K-split partials of h @ W_hh^T

// barrier state (monotonic counters: no reset, replay-safe)
__device__ unsigned g_grp_cnt[NGRP];
__device__ unsigned g_master_cnt = 0;
__device__ unsigned g_bar_sense = 0;
__device__ unsigned g_s_grp[NKS][SGRP];
__device__ unsigned g_s_master[NKS];
__device__ unsigned g_s_sense[NKS];

__device__ __forceinline__ float sigf(float x) { return 1.f / (1.f + expf(-x)); }

__device__ __forceinline__ unsigned ld_acquire_u32(const unsigned* p)
{
    unsigned v;
    asm volatile("ld.acquire.gpu.u32 %0, [%1];" : "=r"(v) : "l"(p) : "memory");
    return v;
}
__device__ __forceinline__ void st_release_u32(unsigned* p, unsigned v)
{
    asm volatile("st.release.gpu.u32 [%0], %1;" :: "l"(p), "r"(v) : "memory");
}

// Full-grid tree barrier: NGRP group counters -> 1 master -> sense.
__device__ __forceinline__ void grid_sync(unsigned* s_sense, int grp)
{
    __syncthreads();
    if (threadIdx.x == 0) {
        const unsigned target = *s_sense + 1u;
        __threadfence();
        const unsigned r = atomicAdd(&g_grp_cnt[grp], 1u);
        if ((r % (NBLK / NGRP)) == (NBLK / NGRP) - 1u) {
            const unsigned m = atomicAdd(&g_master_cnt, 1u);
            if ((m % NGRP) == NGRP - 1u) {
                __threadfence();
                st_release_u32(&g_bar_sense, target);
            }
        }
        while (ld_acquire_u32(&g_bar_sense) != target) { }
        *s_sense = target;
        __threadfence();
    }
    __syncthreads();
}

// Slice-local tree barrier: 48 blocks of one K-slice (6 groups x 8 blocks).
__device__ __forceinline__ void slice_sync(unsigned* s_sense, int slice, int sgrp)
{
    __syncthreads();
    if (threadIdx.x == 0) {
        const unsigned target = *s_sense + 1u;
        __threadfence();
        const unsigned r = atomicAdd(&g_s_grp[slice][sgrp], 1u);
        if ((r % 8u) == 7u) {
            const unsigned m = atomicAdd(&g_s_master[slice], 1u);
            if ((m % SGRP) == SGRP - 1u) {
                __threadfence();
                st_release_u32(&g_s_sense[slice], target);
            }
        }
        while (ld_acquire_u32(&g_s_sense[slice]) != target) { }
        *s_sense = target;
        __threadfence();
    }
    __syncthreads();
}

__device__ __forceinline__ void mma_bf16(float c[4], uint32_t a0, uint32_t a1,
                                         uint32_t a2, uint32_t a3,
                                         uint32_t b0, uint32_t b1)
{
    asm volatile(
        "mma.sync.aligned.m16n8k16.row.col.f32.bf16.bf16.f32 "
        "{%0,%1,%2,%3}, {%4,%5,%6,%7}, {%8,%9}, {%0,%1,%2,%3};"
        : "+f"(c[0]), "+f"(c[1]), "+f"(c[2]), "+f"(c[3])
        : "r"(a0), "r"(a1), "r"(a2), "r"(a3), "r"(b0), "r"(b1));
}

__device__ __forceinline__ void cp_async16(uint32_t saddr, const void* g)
{
    asm volatile("cp.async.cg.shared.global [%0], [%1], 16;" :: "r"(saddr), "l"(g));
}
__device__ __forceinline__ void cp_commit() { asm volatile("cp.async.commit_group;"); }
__device__ __forceinline__ void cp_wait0()  { asm volatile("cp.async.wait_group 0;"); }
__device__ __forceinline__ void cp_wait1()  { asm volatile("cp.async.wait_group 1;"); }

// stage one 64x64 bf16 tile (sync path): thread copies rows r0, r1, 16B chunk q
__device__ __forceinline__ void stage_tile(
    __nv_bfloat16 (*s)[APITCH], const __nv_bfloat16* g, int ld,
    int r0, int r1, int q)
{
    uint4 v = *(const uint4*)(g + (size_t)r0 * ld + q * 8);
    *(uint2*)&s[r0][q * 8]     = make_uint2(v.x, v.y);
    *(uint2*)&s[r0][q * 8 + 4] = make_uint2(v.z, v.w);
    v = *(const uint4*)(g + (size_t)r1 * ld + q * 8);
    *(uint2*)&s[r1][q * 8]     = make_uint2(v.x, v.y);
    *(uint2*)&s[r1][q * 8 + 4] = make_uint2(v.z, v.w);
}

// 64x64x64 bf16x3 compute; A/W are padded-tile base pointers (APITCH stride)
__device__ __forceinline__ void mma_tile(
    float c[4][4],
    const __nv_bfloat16* Ahi, const __nv_bfloat16* Alo,
    const __nv_bfloat16* Whi, const __nv_bfloat16* Wlo,
    int wm, int wn, int gq, int tg)
{
#pragma unroll
    for (int kk = 0; kk < 4; kk++) {
        const int kb = kk * 16 + tg * 2;
        const int ar0 = (wm * 16 + gq) * APITCH;
        const int ar8 = ar0 + 8 * APITCH;
        const uint32_t ahi0 = *(const uint32_t*)&Ahi[ar0 + kb];
        const uint32_t ahi1 = *(const uint32_t*)&Ahi[ar8 + kb];
        const uint32_t ahi2 = *(const uint32_t*)&Ahi[ar0 + kb + 8];
        const uint32_t ahi3 = *(const uint32_t*)&Ahi[ar8 + kb + 8];
        const uint32_t alo0 = *(const uint32_t*)&Alo[ar0 + kb];
        const uint32_t alo1 = *(const uint32_t*)&Alo[ar8 + kb];
        const uint32_t alo2 = *(const uint32_t*)&Alo[ar0 + kb + 8];
        const uint32_t alo3 = *(const uint32_t*)&Alo[ar8 + kb + 8];
#pragma unroll
        for (int nf = 0; nf < 4; nf++) {
            const int nr = (wn * 32 + nf * 8 + gq) * APITCH;
            const uint32_t bhi0 = *(const uint32_t*)&Whi[nr + kb];
            const uint32_t bhi1 = *(const uint32_t*)&Whi[nr + kb + 8];
            const uint32_t blo0 = *(const uint32_t*)&Wlo[nr + kb];
            const uint32_t blo1 = *(const uint32_t*)&Wlo[nr + kb + 8];
            mma_bf16(c[nf], ahi0, ahi1, ahi2, ahi3, bhi0, bhi1);
            mma_bf16(c[nf], ahi0, ahi1, ahi2, ahi3, blo0, blo1);
            mma_bf16(c[nf], alo0, alo1, alo2, alo3, bhi0, bhi1);
        }
    }
}

// ---------------------------------------------------------------------------
// One-time weight splits
// ---------------------------------------------------------------------------
__global__ void split_whh_kernel(const float* __restrict__ W)
{
    const size_t i = (size_t)blockIdx.x * blockDim.x + threadIdx.x;
    if (i < (size_t)G3 * HID) {
        const float w = W[i];
        const __nv_bfloat16 hi = __float2bfloat16(w);
        g_whi[i] = hi;
        g_wlo[i] = __float2bfloat16(w - __bfloat162float(hi));
    }
}

__global__ void split_wih_kernel(const float* __restrict__ W)
{
    const size_t i = (size_t)blockIdx.x * blockDim.x + threadIdx.x;
    if (i < (size_t)G3 * EMB) {
        const float w = W[i];
        const __nv_bfloat16 hi = __float2bfloat16(w);
        g_wihhi[i] = hi;
        g_wihlo[i] = __float2bfloat16(w - __bfloat162float(hi));
    }
}

// ---------------------------------------------------------------------------
// Gather embeddings per token and split to bf16 hi/lo. 1 thread = 4 elements.
// ---------------------------------------------------------------------------
__global__ void gather_split_kernel(const int* __restrict__ text,
                                    const float* __restrict__ emb)
{
    const int i = blockIdx.x * 256 + threadIdx.x;
    const int row = i >> 7;
    const int c4 = (i & 127) * 4;
    const int tok = text[row];
    const float4 v = *(const float4*)(emb + (size_t)tok * EMB + c4);

    const __nv_bfloat16 h0 = __float2bfloat16(v.x);
    const __nv_bfloat16 h1 = __float2bfloat16(v.y);
    const __nv_bfloat16 h2 = __float2bfloat16(v.z);
    const __nv_bfloat16 h3 = __float2bfloat16(v.w);
    const __nv_bfloat16 l0 = __float2bfloat16(v.x - __bfloat162float(h0));
    const __nv_bfloat16 l1 = __float2bfloat16(v.y - __bfloat162float(h1));
    const __nv_bfloat16 l2 = __float2bfloat16(v.z - __bfloat162float(h2));
    const __nv_bfloat16 l3 = __float2bfloat16(v.w - __bfloat162float(h3));

    const size_t off = (size_t)row * EMB + c4;
    __nv_bfloat162 p;
    p.x = h0; p.y = h1; *(__nv_bfloat162*)&g_xehi[off]     = p;
    p.x = h2; p.y = h3; *(__nv_bfloat162*)&g_xehi[off + 2] = p;
    p.x = l0; p.y = l1; *(__nv_bfloat162*)&g_xelo[off]     = p;
    p.x = l2; p.y = l3; *(__nv_bfloat162*)&g_xelo[off + 2] = p;
}

// ---------------------------------------------------------------------------
// xg = xemb @ W_ih^T + b_ih  (M=32768, N=3072, K=512) in bf16x3 tensor cores
// ---------------------------------------------------------------------------
__global__ void __launch_bounds__(256, 2) xg_mma_kernel(const float* __restrict__ bias)
{
    __shared__ __align__(16) __nv_bfloat16 sAhi[64][APITCH];
    __shared__ __align__(16) __nv_bfloat16 sAlo[64][APITCH];
    __shared__ __align__(16) __nv_bfloat16 sBhi[64][APITCH];
    __shared__ __align__(16) __nv_bfloat16 sBlo[64][APITCH];

    const int tid = threadIdx.x;
    const int n0 = blockIdx.x * 64;
    const int m0 = blockIdx.y * 64;

    const int warp = tid >> 5;
    const int lane = tid & 31;
    const int wm = warp >> 1;
    const int wn = warp & 1;
    const int gq = lane >> 2;
    const int tg = lane & 3;

    const int st_row0 = tid >> 3;
    const int st_q0   = tid & 7;
    const int st_row1 = st_row0 + 32;

    float c[4][4];
#pragma unroll
    for (int nf = 0; nf < 4; nf++)
#pragma unroll
        for (int i = 0; i < 4; i++) c[nf][i] = 0.f;

    for (int ch = 0; ch < 8; ch++) {
        const int k0 = ch * 64;
        __syncthreads();
        stage_tile(sAhi, g_xehi + (size_t)m0 * EMB + k0, EMB, st_row0, st_row1, st_q0);
        stage_tile(sAlo, g_xelo + (size_t)m0 * EMB + k0, EMB, st_row0, st_row1, st_q0);
        stage_tile(sBhi, g_wihhi + (size_t)n0 * EMB + k0, EMB, st_row0, st_row1, st_q0);
        stage_tile(sBlo, g_wihlo + (size_t)n0 * EMB + k0, EMB, st_row0, st_row1, st_q0);
        __syncthreads();
        mma_tile(c, &sAhi[0][0], &sAlo[0][0], &sBhi[0][0], &sBlo[0][0], wm, wn, gq, tg);
    }

    const int m0r = m0 + wm * 16 + gq;
#pragma unroll
    for (int nf = 0; nf < 4; nf++) {
        const int n = n0 + wn * 32 + nf * 8 + tg * 2;
        const float b0 = bias[n], b1 = bias[n + 1];
        *(float2*)&g_xg[(size_t)m0r * G3 + n]       = make_float2(c[nf][0] + b0, c[nf][1] + b1);
        *(float2*)&g_xg[(size_t)(m0r + 8) * G3 + n] = make_float2(c[nf][2] + b0, c[nf][3] + b1);
    }
}

// ---------------------------------------------------------------------------
// Persistent kernel (R13 base): 144 blocks, occ-1, W_hh slice resident in
// smem (<=6 chunks); cp.async A double-buffer; full tree barrier after GEMM;
// SLICE-LOCAL barrier after gates (each slice computes gates only for the
// h-range it consumes next step); vectorized float4 gates with hoisted b_hh.
// ---------------------------------------------------------------------------
#define SMEM_BYTES ((12 + 4) * TILE_E * 2)

__global__ void __launch_bounds__(256, 1) gru_persistent(
    const float* __restrict__ b_hh,
    const float* __restrict__ Wfc, const float* __restrict__ bfc,
    float* __restrict__ out)
{
    extern __shared__ __align__(16) __nv_bfloat16 smem[];
    __nv_bfloat16* sW = smem;                 // 12 tiles (chunk*2 + hi/lo)
    __nv_bfloat16* sA = smem + 12 * TILE_E;   // 4 tiles (buf*2 + hi/lo)
    __shared__ unsigned s_sense;

    const int tid = threadIdx.x;
    const int bid = blockIdx.x;
    const int grp = bid % NGRP;

    if (tid == 0) s_sense = ld_acquire_u32(&g_bar_sense);
    __syncthreads();
    unsigned slice_sense = 0;   // per-thread; only tid 0's copy matters

    const int n0 = (bid % 48) * 64;
    const int ks = bid / 48;
    const int k_start = (ks == 0) ? 0 : (ks == 1 ? 384 : 704);
    const int nchunks = (ks == 0) ? 6 : 5;
    const int sgrp = (bid % 48) % SGRP;

    const int warp = tid >> 5;
    const int lane = tid & 31;
    const int wm = warp >> 1;
    const int wn = warp & 1;
    const int gq = lane >> 2;
    const int tg = lane & 3;

    const int st_row0 = tid >> 3;          // 0..31
    const int st_q0   = tid & 7;           // 0..7
    const int st_row1 = st_row0 + 32;      // 32..63

    // ---- gates ownership: slice ks computes h-range [k_start, k_end) ----
    const int wslice = nchunks * 64;               // 384 / 320 / 320
    const int ng_pc  = wslice / 4;                 // float4 groups per batch row
    const int ngroups = ng_pc * BATCH;
    const int gidx = (bid % 48) * 256 + tid;       // 0..12287 within slice
    const bool gact = gidx < ngroups;
    const int gb = gact ? (gidx / ng_pc) : 0;      // batch row
    const int gj = k_start + (gact ? (gidx % ng_pc) : 0) * 4;  // hidden col (x4)

    // hoisted t-invariant gate data
    float4 bh_r = make_float4(0.f, 0.f, 0.f, 0.f);
    float4 bh_z = bh_r, bh_n = bh_r;
    if (gact) {
        bh_r = *(const float4*)&b_hh[gj];
        bh_z = *(const float4*)&b_hh[HID + gj];
        bh_n = *(const float4*)&b_hh[2 * HID + gj];
    }
    const size_t prow = (size_t)gb * G3;
    const int hidx = gb * HID + gj;

    // ---- one-time: load W slice (hi/lo) into resident smem ----
    for (int ch = 0; ch < nchunks; ch++) {
        const int k0 = k_start + ch * 64;
        stage_tile((__nv_bfloat16(*)[APITCH])(sW + (ch * 2 + 0) * TILE_E),
                   g_whi + (size_t)n0 * HID + k0, HID, st_row0, st_row1, st_q0);
        stage_tile((__nv_bfloat16(*)[APITCH])(sW + (ch * 2 + 1) * TILE_E),
                   g_wlo + (size_t)n0 * HID + k0, HID, st_row0, st_row1, st_q0);
    }

    // h0 = 0 (fp32 and bf16 splits)
    for (int i = bid * 256 + tid; i < BATCH * HID; i += NBLK * 256) {
        g_h[0][i] = 0.f;
        g_hhi[i] = __float2bfloat16(0.f);
        g_hlo[i] = __float2bfloat16(0.f);
    }
    grid_sync(&s_sense, grp);   // orders W-staging + h0 before first MMA

    const uint32_t sA_b = (uint32_t)__cvta_generic_to_shared(sA);
    const uint32_t aoff0 = (uint32_t)(st_row0 * APITCH + st_q0 * 8) * 2;
    const uint32_t aoff1 = (uint32_t)(st_row1 * APITCH + st_q0 * 8) * 2;
    const uint32_t tb = (uint32_t)TILE_E * 2;   // tile bytes

    for (int t = 0; t < SEQ; t++) {
        const int par = t & 1;

        // prologue: async-stage A chunk 0 into buf 0
        {
            const int k0 = k_start;
            const __nv_bfloat16* hhi = g_hhi + k0 + st_q0 * 8;
            const __nv_bfloat16* hlo = g_hlo + k0 + st_q0 * 8;
            cp_async16(sA_b + aoff0,          hhi + (size_t)st_row0 * HID);
            cp_async16(sA_b + aoff1,          hhi + (size_t)st_row1 * HID);
            cp_async16(sA_b + tb + aoff0,     hlo + (size_t)st_row0 * HID);
            cp_async16(sA_b + tb + aoff1,     hlo + (size_t)st_row1 * HID);
            cp_commit();
        }

        float c[4][4];
#pragma unroll
        for (int nf = 0; nf < 4; nf++)
#pragma unroll
            for (int i = 0; i < 4; i++) c[nf][i] = 0.f;

        for (int ch = 0; ch < nchunks; ch++) {
            if (ch + 1 < nchunks) {
                const int k0 = k_start + (ch + 1) * 64;
                const uint32_t dst = sA_b + ((ch + 1) & 1) * 2 * tb;
                const __nv_bfloat16* hhi = g_hhi + k0 + st_q0 * 8;
                const __nv_bfloat16* hlo = g_hlo + k0 + st_q0 * 8;
                cp_async16(dst + aoff0,      hhi + (size_t)st_row0 * HID);
                cp_async16(dst + aoff1,      hhi + (size_t)st_row1 * HID);
                cp_async16(dst + tb + aoff0, hlo + (size_t)st_row0 * HID);
                cp_async16(dst + tb + aoff1, hlo + (size_t)st_row1 * HID);
                cp_commit();
                cp_wait1();
            } else {
                cp_wait0();
            }
            __syncthreads();
            const __nv_bfloat16* Ahi = sA + ((ch & 1) * 2 + 0) * TILE_E;
            const __nv_bfloat16* Alo = sA + ((ch & 1) * 2 + 1) * TILE_E;
            const __nv_bfloat16* Whi = sW + (ch * 2 + 0) * TILE_E;
            const __nv_bfloat16* Wlo = sW + (ch * 2 + 1) * TILE_E;
            mma_tile(c, Ahi, Alo, Whi, Wlo, wm, wn, gq, tg);
            __syncthreads();
        }

        // writeback partials
        {
            float* outp = g_part[ks];
            const int m0r = wm * 16 + gq;
#pragma unroll
            for (int nf = 0; nf < 4; nf++) {
                const int n = n0 + wn * 32 + nf * 8 + tg * 2;
                *(float2*)&outp[(size_t)m0r * G3 + n]       = make_float2(c[nf][0], c[nf][1]);
                *(float2*)&outp[(size_t)(m0r + 8) * G3 + n] = make_float2(c[nf][2], c[nf][3]);
            }
        }

        // prefetch xg (overlaps DRAM latency with the barrier wait)
        float4 pxr = make_float4(0.f, 0.f, 0.f, 0.f);
        float4 pxz = pxr, pxn = pxr;
        if (gact) {
            const float* xg = g_xg + ((size_t)t * BATCH + gb) * G3;
            pxr = *(const float4*)&xg[gj];
            pxz = *(const float4*)&xg[HID + gj];
            pxn = *(const float4*)&xg[2 * HID + gj];
        }

        grid_sync(&s_sense, grp);   // full: all parts visible before gates

        // ---- Gates phase (vectorized, slice-owned h-range) ----
        if (gact) {
            float4 hr = bh_r, hz = bh_z, hn = bh_n;
#pragma unroll
            for (int p = 0; p < NKS; p++) {
                const float* pp = g_part[p] + prow;
                const float4 a = *(const float4*)&pp[gj];
                const float4 bq = *(const float4*)&pp[HID + gj];
                const float4 cq = *(const float4*)&pp[2 * HID + gj];
                hr.x += a.x; hr.y += a.y; hr.z += a.z; hr.w += a.w;
                hz.x += bq.x; hz.y += bq.y; hz.z += bq.z; hz.w += bq.w;
                hn.x += cq.x; hn.y += cq.y; hn.z += cq.z; hn.w += cq.w;
            }

            const float r0 = sigf(pxr.x + hr.x), r1 = sigf(pxr.y + hr.y);
            const float r2 = sigf(pxr.z + hr.z), r3 = sigf(pxr.w + hr.w);
            const float z0 = sigf(pxz.x + hz.x), z1 = sigf(pxz.y + hz.y);
            const float z2 = sigf(pxz.z + hz.z), z3 = sigf(pxz.w + hz.w);
            const float n0g = tanhf(pxn.x + r0 * hn.x);
            const float n1g = tanhf(pxn.y + r1 * hn.y);
            const float n2g = tanhf(pxn.z + r2 * hn.z);
            const float n3g = tanhf(pxn.w + r3 * hn.w);

            const float4 hp = *(const float4*)&g_h[par][hidx];
            float4 hw;
            hw.x = (1.f - z0) * n0g + z0 * hp.x;
            hw.y = (1.f - z1) * n1g + z1 * hp.y;
            hw.z = (1.f - z2) * n2g + z2 * hp.z;
            hw.w = (1.f - z3) * n3g + z3 * hp.w;
            *(float4*)&g_h[par ^ 1][hidx] = hw;

            const __nv_bfloat16 e0 = __float2bfloat16(hw.x);
            const __nv_bfloat16 e1 = __float2bfloat16(hw.y);
            const __nv_bfloat16 e2 = __float2bfloat16(hw.z);
            const __nv_bfloat16 e3 = __float2bfloat16(hw.w);
            __nv_bfloat162 hh0; hh0.x = e0; hh0.y = e1;
            __nv_bfloat162 hh1; hh1.x = e2; hh1.y = e3;
            *(__nv_bfloat162*)&g_hhi[hidx]     = hh0;
            *(__nv_bfloat162*)&g_hhi[hidx + 2] = hh1;
            __nv_bfloat162 hl0, hl1;
            hl0.x = __float2bfloat16(hw.x - __bfloat162float(e0));
            hl0.y = __float2bfloat16(hw.y - __bfloat162float(e1));
            hl1.x = __float2bfloat16(hw.z - __bfloat162float(e2));
            hl1.y = __float2bfloat16(hw.w - __bfloat162float(e3));
            *(__nv_bfloat162*)&g_hlo[hidx]     = hl0;
            *(__nv_bfloat162*)&g_hlo[hidx + 2] = hl1;
        }

        slice_sync(&slice_sense, ks, sgrp);   // only this slice's 48 blocks
    }

    grid_sync(&s_sense, grp);   // full: all h ranges visible for FC

    // ---- Final FC (h_last in g_h[0] after t=511) ----
    if (bid < BATCH) {
        const int w = tid >> 5;
        const int ln = tid & 31;
        if (w < NOUT) {
            const float* h = g_h[0] + (size_t)bid * HID;
            const float* wr = Wfc + (size_t)w * HID;
            float s = 0.f;
            for (int k = ln; k < HID; k += 32) s += h[k] * wr[k];
#pragma unroll
            for (int o = 16; o > 0; o >>= 1) s += __shfl_xor_sync(0xffffffff, s, o);
            if (ln == 0) out[bid * NOUT + w] = s + bfc[w];
        }
    }
}

// ---------------------------------------------------------------------------
extern "C" void kernel_launch(void* const* d_in, const int* in_sizes, int n_in,
                              void* d_out, int out_size)
{
    const int*   text  = (const int*)d_in[0];
    const float* emb   = (const float*)d_in[1];
    const float* W_ih  = (const float*)d_in[2];
    const float* W_hh  = (const float*)d_in[3];
    const float* b_ih  = (const float*)d_in[4];
    const float* b_hh  = (const float*)d_in[5];
    const float* W_fc  = (const float*)d_in[6];
    const float* b_fc  = (const float*)d_in[7];
    float* out = (float*)d_out;

    // allow 144KB dynamic smem for the persistent kernel (idempotent)
    cudaFuncSetAttribute(gru_persistent,
                         cudaFuncAttributeMaxDynamicSharedMemorySize, SMEM_BYTES);

    // 0) one-time splits (bf16 hi/lo)
    split_whh_kernel<<<(G3 * HID + 255) / 256, 256>>>(W_hh);
    split_wih_kernel<<<(G3 * EMB + 255) / 256, 256>>>(W_ih);
    gather_split_kernel<<<(MTOT * EMB / 4 + 255) / 256, 256>>>(text, emb);

    // 1) input-side gate activations: bf16x3 tensor-core GEMM
    xg_mma_kernel<<<dim3(48, 512), 256>>>(b_ih);

    // 2) persistent: R13 base + vectorized gates + slice-local barrier 2
    gru_persistent<<<NBLK, 256, SMEM_BYTES>>>(b_hh, W_fc, b_fc, out);
}